// round 10
// baseline (speedup 1.0000x reference)
#include <cuda_runtime.h>
#include <cuda_bf16.h>
#include <stdint.h>

#define BB 4096
#define DD 1024
#define RR 256
#define NCTA 128
#define NTHR 512

#define K_W1 1.3512071919596578
#define K_W0 (-1.7024143839193153)
#define K_C1f ((float)(K_W1 * 0.5))
#define K_C2f ((float)((K_W0 + K_W1) * 0.5))
#define K_DT 0.01f

// -------- device-global scratch (no runtime allocation) --------
__device__ __align__(1024) unsigned char g_Ub[16 * 32768];   // U bf16: 16 k-chunks [256n x 64k] SW128
__device__ __align__(1024) unsigned char g_Wb[64 * 8192];    // W bf16: 16 n-chunks x 4 k-tiles [64n x 64k] SW128
__device__ __align__(1024) float g_vf[(size_t)BB * DD];      // v fp32 master

// -------- helpers --------
__device__ __forceinline__ uint32_t swz(uint32_t o) { return o ^ ((o >> 3) & 0x70); }
__device__ __forceinline__ uint32_t s2u(const void* p) {
    uint32_t a; asm("{ .reg .u64 t; cvta.to.shared.u64 t, %1; cvt.u32.u64 %0, t; }" : "=r"(a) : "l"(p)); return a;
}
__device__ __forceinline__ uint32_t bf2u(__nv_bfloat162 b) { return *reinterpret_cast<uint32_t*>(&b); }
__device__ __forceinline__ void mb_init(uint32_t a, uint32_t c) {
    asm volatile("mbarrier.init.shared.b64 [%0], %1;" :: "r"(a), "r"(c) : "memory");
}
__device__ __forceinline__ void mb_expect(uint32_t a, uint32_t b) {
    asm volatile("mbarrier.arrive.expect_tx.shared.b64 _, [%0], %1;" :: "r"(a), "r"(b) : "memory");
}
__device__ __forceinline__ void mb_wait(uint32_t a, uint32_t p) {
    asm volatile("{\n\t.reg .pred P;\n\tLW%=:\n\t"
        "mbarrier.try_wait.parity.acquire.cta.shared::cta.b64 P, [%0], %1, 0x989680;\n\t"
        "@P bra LD%=;\n\tbra LW%=;\n\tLD%=:\n\t}" :: "r"(a), "r"(p) : "memory");
}
__device__ __forceinline__ void bulkcp(uint32_t d, const void* s, uint32_t n, uint32_t mb) {
    asm volatile("cp.async.bulk.shared::cluster.global.mbarrier::complete_tx::bytes [%0], [%1], %2, [%3];"
                 :: "r"(d), "l"(s), "r"(n), "r"(mb) : "memory");
}
__device__ __forceinline__ void fence_async_sh() { asm volatile("fence.proxy.async.shared::cta;" ::: "memory"); }
__device__ __forceinline__ void nbar_sync(int id, int cnt) {
    asm volatile("bar.sync %0, %1;" :: "r"(id), "r"(cnt) : "memory");
}
__device__ __forceinline__ void nbar_arrive(int id, int cnt) {
    asm volatile("bar.arrive %0, %1;" :: "r"(id), "r"(cnt) : "memory");
}
__device__ __forceinline__ void ldsm4(uint32_t* r, uint32_t a) {
    asm volatile("ldmatrix.sync.aligned.m8n8.x4.shared.b16 {%0,%1,%2,%3}, [%4];"
                 : "=r"(r[0]), "=r"(r[1]), "=r"(r[2]), "=r"(r[3]) : "r"(a));
}
__device__ __forceinline__ void mma16816(float* c, const uint32_t* a, const uint32_t* b) {
    asm volatile("mma.sync.aligned.m16n8k16.row.col.f32.bf16.bf16.f32 "
        "{%0,%1,%2,%3}, {%4,%5,%6,%7}, {%8,%9}, {%0,%1,%2,%3};"
        : "+f"(c[0]), "+f"(c[1]), "+f"(c[2]), "+f"(c[3])
        : "r"(a[0]), "r"(a[1]), "r"(a[2]), "r"(a[3]), "r"(b[0]), "r"(b[1]));
}
__device__ __forceinline__ void sts32(uint32_t a, uint32_t v) {
    asm volatile("st.shared.b32 [%0], %1;" :: "r"(a), "r"(v) : "memory");
}
__device__ __forceinline__ void sts64(uint32_t a, uint32_t v0, uint32_t v1) {
    asm volatile("st.shared.v2.u32 [%0], {%1, %2};" :: "r"(a), "r"(v0), "r"(v1) : "memory");
}
__device__ __forceinline__ const unsigned char* chunk_src(int g) {
    int l = g & 31;
    return (l < 16) ? (g_Ub + (size_t)l * 32768) : (g_Wb + (size_t)(l - 16) * 32768);
}

// -------- prologue: fp32 -> bf16 SW128 tiles in gmem --------
__global__ void prep_uw_kernel(const float* __restrict__ U, const float* __restrict__ W) {
    int idx = blockIdx.x * blockDim.x + threadIdx.x;       // 262144
    if (idx < 131072) {
        int kc = idx >> 13, rem = idx & 8191, r = rem >> 5, j = rem & 31;
        float2 f = *(const float2*)(U + (size_t)r * DD + kc * 64 + j * 2);
        *(uint32_t*)(g_Ub + kc * 32768 + swz((uint32_t)(r * 128 + j * 4))) = bf2u(__float22bfloat162_rn(f));
    } else {
        int i2 = idx - 131072;
        int t = i2 >> 11, rem = i2 & 2047, dr = rem >> 5, j = rem & 31;
        int nc = t >> 2, kt = t & 3;
        float2 f = *(const float2*)(W + (size_t)(nc * 64 + dr) * RR + kt * 64 + j * 2);
        *(uint32_t*)(g_Wb + t * 8192 + swz((uint32_t)(dr * 128 + j * 4))) = bf2u(__float22bfloat162_rn(f));
    }
}

// -------- main fused integrator --------
__global__ __launch_bounds__(NTHR, 1)
void yoshida_mma7_kernel(const float* __restrict__ x, const float* __restrict__ v,
                         const float* __restrict__ force, float* __restrict__ out) {
    extern __shared__ unsigned char dsm[];
    unsigned char* basep = (unsigned char*)(((uintptr_t)dsm + 1023u) & ~(uintptr_t)1023u);
    const uint32_t base = s2u(basep);
    const uint32_t SV   = base;                 // 64KB resident v bf16: 16 tiles [32 x 64] SW128
    const uint32_t RING = base + 65536u;        // 4 x 32KB unified U/W chunk ring
    const uint32_t H2   = base + 196608u;       // 4 x 4KB h^2 tiles [32 x 64] bf16 SW128
    unsigned char* SGB  = basep + 212992u;      // sGamma bf16: 4 quad-quarters [32 x 64], pitch 136B
    const uint32_t SGu  = base + 212992u;
    const uint32_t BARS = base + 230400u;       // full[4]

    const int tid = threadIdx.x, wid = tid >> 5, lid = tid & 31;
    const int mh = wid >> 3;                   // GEMM1 M half
    const int q  = wid & 7;                    // GEMM1 N octant
    const int quad = wid & 3;                  // GEMM2: ring-buffer / chunk owner
    const int w4 = wid >> 2;
    const int mh2 = w4 & 1;                    // GEMM2 M half
    const int nn  = w4 >> 1;                   // GEMM2 N 32-half within chunk
    const int row0 = blockIdx.x * 32;

    const uint32_t arow  = (uint32_t)((mh  * 16 + (lid & 15)) * 128 + ((lid >> 4) << 4));
    const uint32_t arow2 = (uint32_t)((mh2 * 16 + (lid & 15)) * 128 + ((lid >> 4) << 4));
    const uint32_t brow  = (uint32_t)(((lid & 7) + ((lid >> 4) << 3)) * 128 + (((lid >> 3) & 1) << 4));
    const int hr = lid >> 2, hc2 = (lid & 3) * 2;
    // GEMM2 quad-local ew mapping
    const int qlane = w4 * 32 + lid;
    const int ewr = qlane >> 2, ewc = qlane & 3;
    const size_t egrow = (size_t)(row0 + ewr) * DD;

    if (tid == 0) {
        #pragma unroll
        for (int i = 0; i < 4; ++i) mb_init(BARS + 8u * i, 1);
        fence_async_sh();
        #pragma unroll
        for (int c = 0; c < 4; ++c) {
            mb_expect(BARS + 8u * c, 32768u);
            bulkcp(RING + (uint32_t)c * 32768u, chunk_src(c), 32768u, BARS + 8u * c);
        }
    }

    // resident sV init: bf16(v) pre-swizzled
    for (int i = tid; i < 8192; i += NTHR) {
        int row = i >> 8, rem = i & 255, kc = rem >> 4, jj = rem & 15;
        float4 f = *(const float4*)(v + (size_t)(row0 + row) * DD + kc * 64 + jj * 4);
        sts64(SV + (uint32_t)kc * 4096u + swz((uint32_t)(row * 128 + jj * 8)),
              bf2u(__float22bfloat162_rn(make_float2(f.x, f.y))),
              bf2u(__float22bfloat162_rn(make_float2(f.z, f.w))));
    }
    __syncthreads();

    const float dctab[3] = { (float)K_W1 * K_DT, (float)K_W0 * K_DT, (float)K_W1 * K_DT };

    for (int step = 0; step < 3; ++step) {
        const float dcoef = dctab[step];
        const float* vsrc = (step == 0) ? v : g_vf;

        // ===== GEMM1: free-running chunk-pairs; producer warp 15 gates refills =====
        float acc1[4][4];
        #pragma unroll
        for (int t = 0; t < 4; ++t)
            #pragma unroll
            for (int j = 0; j < 4; ++j) acc1[t][j] = 0.f;

        for (int kp = 0; kp < 8; ++kp) {
            const int g = step * 32 + kp * 2;
            const int b0 = (kp * 2) & 3;
            const uint32_t ph = (uint32_t)((g >> 2) & 1);
            mb_wait(BARS + 8u * b0, ph);
            mb_wait(BARS + 8u * (b0 + 1), ph);
            #pragma unroll
            for (int cc = 0; cc < 2; ++cc) {
                const uint32_t Ab = SV + (uint32_t)(kp * 2 + cc) * 4096u;
                const uint32_t Bb = RING + (uint32_t)(b0 + cc) * 32768u;
                #pragma unroll
                for (int ks = 0; ks < 4; ++ks) {
                    uint32_t a[4];
                    ldsm4(a, Ab + swz(arow + ks * 32));
                    #pragma unroll
                    for (int ntp = 0; ntp < 2; ++ntp) {
                        uint32_t bb[4];
                        ldsm4(bb, Bb + swz(brow + (uint32_t)((q * 32 + ntp * 16) * 128) + ks * 32));
                        mma16816(acc1[2 * ntp],     a, bb);
                        mma16816(acc1[2 * ntp + 1], a, bb + 2);
                    }
                }
            }
            const int bid = 1 + (kp & 1);
            if (wid == 15) {
                nbar_sync(bid, 512);           // all warps consumed this pair
                if (lid == 0) {
                    mb_expect(BARS + 8u * b0, 32768u);
                    bulkcp(RING + (uint32_t)b0 * 32768u, chunk_src(g + 4), 32768u, BARS + 8u * b0);
                    mb_expect(BARS + 8u * (b0 + 1), 32768u);
                    bulkcp(RING + (uint32_t)(b0 + 1) * 32768u, chunk_src(g + 5), 32768u, BARS + 8u * (b0 + 1));
                }
            } else {
                nbar_arrive(bid, 512);         // non-blocking
            }
        }

        // ---- h^2 -> bf16 SW128 H2 tiles (per-warp, own acc1) ----
        {
            const uint32_t ht = H2 + (uint32_t)(q >> 1) * 4096u;
            #pragma unroll
            for (int t = 0; t < 4; ++t) {
                const int ntp = t >> 1, half = t & 1;
                float c0 = acc1[t][0], c1 = acc1[t][1], c2 = acc1[t][2], c3 = acc1[t][3];
                uint32_t p0 = bf2u(__float22bfloat162_rn(make_float2(c0 * c0, c1 * c1)));
                uint32_t p1 = bf2u(__float22bfloat162_rn(make_float2(c2 * c2, c3 * c3)));
                uint32_t koff = (uint32_t)(((q & 1) * 32 + ntp * 16 + half * 8 + hc2) * 2);
                sts32(ht + swz((uint32_t)((mh * 16 + hr) * 128) + koff), p0);
                sts32(ht + swz((uint32_t)((mh * 16 + hr + 8) * 128) + koff), p1);
            }
        }
        __syncthreads();    // H2 visible to all before GEMM2

        // ===== GEMM2: independent quads — quad owns buffer, SG quarter, ew cols =====
        for (int g4 = 0; g4 < 4; ++g4) {
            const int c = g4 * 4 + quad;
            const int g = step * 32 + 16 + c;
            mb_wait(BARS + 8u * quad, (uint32_t)((g >> 2) & 1));

            float acc2[4][4];
            #pragma unroll
            for (int t = 0; t < 4; ++t)
                #pragma unroll
                for (int j = 0; j < 4; ++j) acc2[t][j] = 0.f;

            const uint32_t Bb = RING + (uint32_t)quad * 32768u;
            #pragma unroll
            for (int kt = 0; kt < 4; ++kt) {
                const uint32_t At = H2 + (uint32_t)kt * 4096u;
                const uint32_t Bt = Bb + (uint32_t)kt * 8192u;
                #pragma unroll
                for (int ks = 0; ks < 4; ++ks) {
                    uint32_t a[4];
                    ldsm4(a, At + swz(arow2 + ks * 32));
                    #pragma unroll
                    for (int ntp = 0; ntp < 2; ++ntp) {
                        uint32_t bb[4];
                        ldsm4(bb, Bt + swz(brow + (uint32_t)((nn * 32 + ntp * 16) * 128) + ks * 32));
                        mma16816(acc2[2 * ntp],     a, bb);
                        mma16816(acc2[2 * ntp + 1], a, bb + 2);
                    }
                }
            }
            nbar_sync(3 + quad, 128);          // quad: MMA done + prev ew done (SG reusable)
            if (wid == quad && lid == 0 && g + 4 < 96) {
                mb_expect(BARS + 8u * quad, 32768u);
                bulkcp(Bb, chunk_src(g + 4), 32768u, BARS + 8u * quad);
            }
            // stage this quad's 64 cols (bf16, pitch 136B)
            {
                const uint32_t SGq = SGu + (uint32_t)quad * 4352u;
                #pragma unroll
                for (int t = 0; t < 4; ++t) {
                    const uint32_t co = (uint32_t)((nn * 32 + t * 8 + hc2) * 2);
                    sts32(SGq + (uint32_t)((mh2 * 16 + hr) * 136) + co,
                          bf2u(__float22bfloat162_rn(make_float2(acc2[t][0], acc2[t][1]))));
                    sts32(SGq + (uint32_t)((mh2 * 16 + hr + 8) * 136) + co,
                          bf2u(__float22bfloat162_rn(make_float2(acc2[t][2], acc2[t][3]))));
                }
            }
            nbar_sync(3 + quad, 128);          // staging visible within quad

            // quad-local ew over chunk c's 64 cols: 4 float4 per thread
            {
                const unsigned char* SGr = SGB + (size_t)quad * 4352 + (size_t)ewr * 136;
                #pragma unroll
                for (int i = 0; i < 4; ++i) {
                    const int f4 = ewc + 4 * i;
                    const int d = c * 64 + f4 * 4;
                    uint2 gw = *(const uint2*)(SGr + f4 * 8);
                    float2 ga = __bfloat1622float2(*(__nv_bfloat162*)&gw.x);
                    float2 gb = __bfloat1622float2(*(__nv_bfloat162*)&gw.y);
                    float4 f4v = *(const float4*)(force + egrow + d);
                    float4 v4 = *(const float4*)(vsrc + egrow + d);
                    float4 vn;
                    vn.x = v4.x + dcoef * (f4v.x - ga.x);
                    vn.y = v4.y + dcoef * (f4v.y - ga.y);
                    vn.z = v4.z + dcoef * (f4v.z - gb.x);
                    vn.w = v4.w + dcoef * (f4v.w - gb.y);
                    *(float4*)(g_vf + egrow + d) = vn;
                    sts64(SV + (uint32_t)c * 4096u + swz((uint32_t)(ewr * 128 + f4 * 8)),
                          bf2u(__float22bfloat162_rn(make_float2(vn.x, vn.y))),
                          bf2u(__float22bfloat162_rn(make_float2(vn.z, vn.w))));
                    float4* ox = (float4*)(out + egrow + d);
                    if (step == 0) {
                        float4 t;
                        t.x = K_C1f * v4.x + K_C2f * vn.x; t.y = K_C1f * v4.y + K_C2f * vn.y;
                        t.z = K_C1f * v4.z + K_C2f * vn.z; t.w = K_C1f * v4.w + K_C2f * vn.w;
                        *ox = t;
                    } else if (step == 1) {
                        float4 t = *ox;
                        t.x += K_C2f * vn.x; t.y += K_C2f * vn.y;
                        t.z += K_C2f * vn.z; t.w += K_C2f * vn.w;
                        *ox = t;
                    } else {
                        float4 t = *ox;
                        float4 x4 = *(const float4*)(x + egrow + d);
                        t.x = x4.x + K_DT * (t.x + K_C1f * vn.x);
                        t.y = x4.y + K_DT * (t.y + K_C1f * vn.y);
                        t.z = x4.z + K_DT * (t.z + K_C1f * vn.z);
                        t.w = x4.w + K_DT * (t.w + K_C1f * vn.w);
                        *ox = t;
                        *(float4*)(out + (size_t)BB * DD + egrow + d) = vn;
                    }
                }
            }
        }
        __syncthreads();    // SV fully updated before next step's GEMM1 reads
    }
}

extern "C" void kernel_launch(void* const* d_in, const int* in_sizes, int n_in,
                              void* d_out, int out_size)
{
    const float* x     = (const float*)d_in[0];
    const float* v     = (const float*)d_in[1];
    const float* force = (const float*)d_in[2];
    const float* U     = (const float*)d_in[3];
    const float* W     = (const float*)d_in[4];
    float* out = (float*)d_out;

    const int smem_bytes = 231456;
    cudaFuncSetAttribute(yoshida_mma7_kernel, cudaFuncAttributeMaxDynamicSharedMemorySize, smem_bytes);

    prep_uw_kernel<<<1024, 256>>>(U, W);
    yoshida_mma7_kernel<<<NCTA, NTHR, smem_bytes>>>(x, v, force, out);
}